// round 3
// baseline (speedup 1.0000x reference)
#include <cuda_runtime.h>
#include <cstdint>

#define MQ     50000
#define NSUP   100000
#define HN     32
#define KPN    15
#define CIN    64
#define COUT   64
#define MB     16
#define NTHR   256
#define INFPT  1.0e6f

typedef unsigned long long ull;

// smem region sizes (words)
#define TILE_W   (64 * 66)                  // 4224: padded Wt tile
#define WS_WORDS (2 * TILE_W)               // 8448: holds w rows (8192) / Wt ping-pong / partials (8192)
#define SMEM_WORDS (WS_WORDS + MB*KPN*CIN + 48 + MB + MB*HN)
#define SMEM_BYTES (SMEM_WORDS * 4)

__device__ int g_idx_is64;
__device__ unsigned char g_flags[NSUP];
__device__ float g_Wt[KPN * COUT * CIN];    // transposed weights [k][d][c]

// ---------------- f32x2 helpers ----------------
__device__ __forceinline__ ull dup2(float v) {
    ull r; asm("mov.b64 %0, {%1, %1};" : "=l"(r) : "f"(v)); return r;
}
__device__ __forceinline__ void fma2(ull& d, ull a, ull b) {
    asm("fma.rn.f32x2 %0, %1, %2, %0;" : "+l"(d) : "l"(a), "l"(b));
}
__device__ __forceinline__ float2 unpk(ull v) {
    float2 r; asm("mov.b64 {%0, %1}, %2;" : "=f"(r.x), "=f"(r.y) : "l"(v)); return r;
}

// ---------------- prep: flags + W transpose + idx dtype detect ----------------
#define FLAG_BLKS ((NSUP + 7) / 8)
__global__ void __launch_bounds__(256) prep_kernel(const float* __restrict__ sfeats,
                                                   const float* __restrict__ wts,
                                                   const unsigned* __restrict__ nbr) {
    __shared__ float ts[64 * 68];
    const int b = blockIdx.x;
    const int tid = threadIdx.x;

    if (b < FLAG_BLKS) {
        const int n = b * 8 + (tid >> 5);
        if (n >= NSUP) return;
        const int lane = tid & 31;
        const float* row = sfeats + (long long)n * CIN;
        float s = row[lane] + row[lane + 32];
        #pragma unroll
        for (int o = 16; o; o >>= 1) s += __shfl_xor_sync(0xffffffffu, s, o);
        if (lane == 0) g_flags[n] = (s > 0.0f) ? 1 : 0;
        return;
    }
    if (b < FLAG_BLKS + KPN) {
        const int k = b - FLAG_BLKS;
        const float4* src = (const float4*)(wts + k * 4096);
        #pragma unroll
        for (int j = 0; j < 4; j++) {
            const int e4 = j * 256 + tid;
            const float4 v = src[e4];
            const int c = e4 >> 4;
            const int d = (e4 & 15) * 4;
            *(float4*)(ts + c * 68 + d) = v;
        }
        __syncthreads();
        float4* dst = (float4*)(g_Wt + k * 4096);
        #pragma unroll
        for (int j = 0; j < 4; j++) {
            const int o4 = j * 256 + tid;
            const int d = o4 >> 4;
            const int c = (o4 & 15) * 4;
            dst[o4] = make_float4(ts[(c + 0) * 68 + d], ts[(c + 1) * 68 + d],
                                  ts[(c + 2) * 68 + d], ts[(c + 3) * 68 + d]);
        }
        return;
    }
    // detect int64 vs int32 neighbor indices
    if (tid == 0) {
        int is64 = 1;
        #pragma unroll
        for (int i = 0; i < 64; i++) {
            if (nbr[2 * i + 1] != 0u) { is64 = 0; break; }
        }
        g_idx_is64 = is64;
    }
}

// ---------------- main fused kernel ----------------
extern "C" __global__ void __launch_bounds__(NTHR, 2)
kpconv_kernel(const float* __restrict__ qpts,
              const float* __restrict__ spts,
              const float* __restrict__ sfeats,
              const void*  __restrict__ nbr,
              const float* __restrict__ kpts,
              float* __restrict__ out)
{
    extern __shared__ float sm[];
    float* w_s   = sm;                          // WS_WORDS: w rows / Wt tiles / partials
    float* wgt_s = sm + WS_WORDS;               // [MB][KPN][CIN]
    float* kp_s  = wgt_s + MB * KPN * CIN;      // 48
    float* inv_s = kp_s + 48;                   // MB
    int*   idx_s = (int*)(inv_s + MB);          // [MB][HN]

    const int tid = threadIdx.x;
    const int m0  = blockIdx.x * MB;
    const bool is64 = (g_idx_is64 != 0);

    if (tid < KPN * 3) kp_s[tid] = kpts[tid];
    __syncthreads();

    // ---------------- Stage A: geometry weights w[m,h,k] -> smem ------------
    #pragma unroll
    for (int it = 0; it < 2; it++) {
        const int p = tid + it * NTHR;          // p < MB*HN = 512
        const int m = p >> 5;
        const int h = p & 31;
        const long long gi = (long long)(m0 + m) * HN + h;
        int idx;
        if (is64) idx = (int)((const long long*)nbr)[gi];
        else      idx = ((const int*)nbr)[gi];
        const bool valid = (idx < NSUP);

        float px, py, pz;
        if (valid) {
            const float* s3 = spts + (long long)idx * 3;
            px = s3[0]; py = s3[1]; pz = s3[2];
        } else {
            px = INFPT; py = INFPT; pz = INFPT;
        }
        const float* q3 = qpts + (long long)(m0 + m) * 3;
        const float rx = px - q3[0];
        const float ry = py - q3[1];
        const float rz = pz - q3[2];

        float* wrow = w_s + p * 16;
        float wmax = 0.0f;
        #pragma unroll
        for (int k = 0; k < KPN; k++) {
            const float dx = rx - kp_s[k * 3 + 0];
            const float dy = ry - kp_s[k * 3 + 1];
            const float dz = rz - kp_s[k * 3 + 2];
            const float sq = dx * dx + dy * dy + dz * dz;
            const float w  = fmaxf(1.0f - sqrtf(sq) * 0.5f, 0.0f);
            wrow[k] = w;
            wmax = fmaxf(wmax, w);
        }
        wrow[15] = 0.0f;   // padding kernel-point slot for k-pair FFMA2

        bool real = false;
        if (valid) real = (g_flags[idx] != 0);
        const unsigned bal = __ballot_sync(0xffffffffu, real);
        if ((tid & 31) == 0) inv_s[m] = 1.0f / (float)max(__popc(bal), 1);

        idx_s[p] = (wmax > 0.0f) ? idx : -1;    // sentinel: skip in stage B
    }
    __syncthreads();

    // ---------------- Stage B: weighted[m,k,c] = sum_h w * f (FFMA2, k-pairs)
    {
        const int g  = tid >> 4;
        const int j  = tid & 15;
        const int c0 = j * 4;

        ull acc2[8][4];
        #pragma unroll
        for (int kp = 0; kp < 8; kp++)
            #pragma unroll
            for (int c = 0; c < 4; c++) acc2[kp][c] = 0ull;

        const int*   irow  = idx_s + g * HN;
        const float* wbase = w_s + g * HN * 16;

        #pragma unroll 4
        for (int h = 0; h < HN; h++) {
            const int idx = irow[h];
            if (idx >= 0) {
                const float4 f = *(const float4*)(sfeats + (long long)idx * CIN + c0);
                ull fd[4];
                fd[0] = dup2(f.x); fd[1] = dup2(f.y); fd[2] = dup2(f.z); fd[3] = dup2(f.w);
                const ull* wr = (const ull*)(wbase + h * 16);
                #pragma unroll
                for (int kp = 0; kp < 8; kp++) {
                    const ull wp = wr[kp];     // (w[2kp], w[2kp+1]) broadcast LDS.64
                    fma2(acc2[kp][0], wp, fd[0]);
                    fma2(acc2[kp][1], wp, fd[1]);
                    fma2(acc2[kp][2], wp, fd[2]);
                    fma2(acc2[kp][3], wp, fd[3]);
                }
            }
        }

        float* wgrow = wgt_s + g * KPN * CIN + c0;
        #pragma unroll
        for (int kp = 0; kp < 8; kp++) {
            #pragma unroll
            for (int c = 0; c < 4; c++) {
                const float2 v = unpk(acc2[kp][c]);
                wgrow[(2 * kp) * CIN + c] = v.x;
                if (kp < 7) wgrow[(2 * kp + 1) * CIN + c] = v.y;
            }
        }
    }
    __syncthreads();   // wgt_s ready; w_s free for Wt tiles

    // ---------------- Stage C: out[m,d] = sum_{k,c} weighted * Wt (FFMA2) ---
    {
        const int dq = tid & 15;          // owns d = {dq, dq+16, dq+32, dq+48}
        const int mh = (tid >> 4) & 1;    // query half
        const int cg = tid >> 5;          // 8 channel groups of 8
        const int c0 = cg * 8;

        ull acc2[8][4];                   // [mb][d-index i]; lanes = (c-even, c-odd) partials
        #pragma unroll
        for (int mb = 0; mb < 8; mb++)
            #pragma unroll
            for (int i = 0; i < 4; i++) acc2[mb][i] = 0ull;

        // staging: tile k -> w_s[ (k&1)*TILE_W ], rows padded to 66
        float4 stg[4];
        {
            const float4* src = (const float4*)g_Wt;
            #pragma unroll
            for (int j = 0; j < 4; j++) stg[j] = src[j * 256 + tid];
            #pragma unroll
            for (int j = 0; j < 4; j++) {
                const int e4 = j * 256 + tid;
                float* p = w_s + (e4 >> 4) * 66 + (e4 & 15) * 4;
                ((float2*)p)[0] = make_float2(stg[j].x, stg[j].y);
                ((float2*)p)[1] = make_float2(stg[j].z, stg[j].w);
            }
        }

        const float* wgbase = wgt_s + (mh * 8) * (KPN * CIN) + c0;

        #pragma unroll 1
        for (int k = 0; k < KPN; k++) {
            if (k + 1 < KPN) {
                const float4* src = (const float4*)(g_Wt + (k + 1) * 4096);
                #pragma unroll
                for (int j = 0; j < 4; j++) stg[j] = src[j * 256 + tid];
            }
            __syncthreads();
            if (k + 1 < KPN) {
                float* buf = w_s + ((k + 1) & 1) * TILE_W;
                #pragma unroll
                for (int j = 0; j < 4; j++) {
                    const int e4 = j * 256 + tid;
                    float* p = buf + (e4 >> 4) * 66 + (e4 & 15) * 4;
                    ((float2*)p)[0] = make_float2(stg[j].x, stg[j].y);
                    ((float2*)p)[1] = make_float2(stg[j].z, stg[j].w);
                }
            }
            // compute tile k
            const float* tb = w_s + (k & 1) * TILE_W;
            ull wt[4][4];
            #pragma unroll
            for (int i = 0; i < 4; i++) {
                const float* rp = tb + (i * 16 + dq) * 66 + c0;
                #pragma unroll
                for (int cp = 0; cp < 4; cp++)
                    wt[i][cp] = *(const ull*)(rp + 2 * cp);   // conflict-free LDS.64
            }
            const float* wk = wgbase + k * CIN;
            #pragma unroll
            for (int mb = 0; mb < 8; mb++) {
                const ull* wvp = (const ull*)(wk + mb * (KPN * CIN));
                const ull w0 = wvp[0], w1 = wvp[1], w2 = wvp[2], w3 = wvp[3];
                #pragma unroll
                for (int i = 0; i < 4; i++) {
                    fma2(acc2[mb][i], w0, wt[i][0]);
                    fma2(acc2[mb][i], w1, wt[i][1]);
                    fma2(acc2[mb][i], w2, wt[i][2]);
                    fma2(acc2[mb][i], w3, wt[i][3]);
                }
            }
        }

        __syncthreads();   // all tile reads done; w_s -> partial buffer [8][16][64]
        #pragma unroll
        for (int mb = 0; mb < 8; mb++) {
            #pragma unroll
            for (int i = 0; i < 4; i++) {
                const float2 v = unpk(acc2[mb][i]);
                w_s[cg * 1024 + (mh * 8 + mb) * 64 + i * 16 + dq] = v.x + v.y;
            }
        }
    }
    __syncthreads();

    // final cross-group reduction + normalize + store
    {
        const int mb = tid >> 4;
        const int d0 = (tid & 15) * 4;
        float4 o = make_float4(0.f, 0.f, 0.f, 0.f);
        #pragma unroll
        for (int g8 = 0; g8 < 8; g8++) {
            const float4 p = *(const float4*)(w_s + g8 * 1024 + mb * 64 + d0);
            o.x += p.x; o.y += p.y; o.z += p.z; o.w += p.w;
        }
        const float inv = inv_s[mb];
        o.x *= inv; o.y *= inv; o.z *= inv; o.w *= inv;
        *(float4*)(out + (long long)(m0 + mb) * COUT + d0) = o;
    }
}

extern "C" void kernel_launch(void* const* d_in, const int* in_sizes, int n_in,
                              void* d_out, int out_size) {
    const float* qpts = nullptr;   // 150000
    const float* spts = nullptr;   // 300000
    const float* sfeats = nullptr; // 6400000
    const void*  nbr = nullptr;    // 1600000
    const float* wts = nullptr;    // 61440
    const float* kpts = nullptr;   // 45
    for (int i = 0; i < n_in; i++) {
        switch (in_sizes[i]) {
            case MQ * 3:        qpts   = (const float*)d_in[i]; break;
            case NSUP * 3:      spts   = (const float*)d_in[i]; break;
            case NSUP * CIN:    sfeats = (const float*)d_in[i]; break;
            case MQ * HN:       nbr    = d_in[i];               break;
            case KPN*CIN*COUT:  wts    = (const float*)d_in[i]; break;
            case KPN * 3:       kpts   = (const float*)d_in[i]; break;
            default: break;
        }
    }
    float* outp = (float*)d_out;

    cudaFuncSetAttribute(kpconv_kernel,
                         cudaFuncAttributeMaxDynamicSharedMemorySize, SMEM_BYTES);

    prep_kernel<<<FLAG_BLKS + KPN + 1, 256>>>(sfeats, wts, (const unsigned*)nbr);
    kpconv_kernel<<<MQ / MB, NTHR, SMEM_BYTES>>>(
        qpts, spts, sfeats, nbr, kpts, outp);
}

// round 4
// speedup vs baseline: 1.1683x; 1.1683x over previous
#include <cuda_runtime.h>
#include <cstdint>

#define MQ     50000
#define NSUP   100000
#define HN     32
#define KPN    15
#define CIN    64
#define COUT   64
#define MB     16
#define NTHR   256
#define INFPT  1.0e6f

typedef unsigned long long ull;

// smem layout (words): w_s[MB][HN][16]=8192 (reused for partials [8][16][64]=8192)
//                      wgt_s[MB][KPN][CIN]=15360, kp_s 48, inv_s MB, idx_s MB*HN
#define WS_WORDS 8192
#define SMEM_WORDS (WS_WORDS + MB*KPN*CIN + 48 + MB + MB*HN)
#define SMEM_BYTES (SMEM_WORDS * 4)

__device__ int g_idx_is64;
__device__ unsigned char g_flags[NSUP];
// packed transposed weights: g_Wp[k][cg(8)][i(4)][cp(4)][dq(16)][2]
//   value = W[k][c=8*cg+2*cp+e][d=16*i+dq]
__device__ float g_Wp[KPN * COUT * CIN];

// ---------------- f32x2 helpers ----------------
__device__ __forceinline__ ull dup2(float v) {
    ull r; asm("mov.b64 %0, {%1, %1};" : "=l"(r) : "f"(v)); return r;
}
__device__ __forceinline__ void fma2(ull& d, ull a, ull b) {
    asm("fma.rn.f32x2 %0, %1, %2, %0;" : "+l"(d) : "l"(a), "l"(b));
}
__device__ __forceinline__ float2 unpk(ull v) {
    float2 r; asm("mov.b64 {%0, %1}, %2;" : "=f"(r.x), "=f"(r.y) : "l"(v)); return r;
}

// ---------------- prep: flags + W pack + idx dtype detect ----------------
#define FLAG_BLKS ((NSUP + 7) / 8)
__global__ void __launch_bounds__(256) prep_kernel(const float* __restrict__ sfeats,
                                                   const float* __restrict__ wts,
                                                   const unsigned* __restrict__ nbr) {
    __shared__ float ts[64 * 68];
    const int b = blockIdx.x;
    const int tid = threadIdx.x;

    if (b < FLAG_BLKS) {
        const int n = b * 8 + (tid >> 5);
        if (n >= NSUP) return;
        const int lane = tid & 31;
        const float* row = sfeats + (long long)n * CIN;
        float s = row[lane] + row[lane + 32];
        #pragma unroll
        for (int o = 16; o; o >>= 1) s += __shfl_xor_sync(0xffffffffu, s, o);
        if (lane == 0) g_flags[n] = (s > 0.0f) ? 1 : 0;
        return;
    }
    if (b < FLAG_BLKS + KPN) {
        const int k = b - FLAG_BLKS;
        // stage W[k] into smem as ts[c*68 + d]
        const float4* src = (const float4*)(wts + k * 4096);
        #pragma unroll
        for (int j = 0; j < 4; j++) {
            const int e4 = j * 256 + tid;
            const float4 v = src[e4];
            const int c = e4 >> 4;
            const int d = (e4 & 15) * 4;
            *(float4*)(ts + c * 68 + d) = v;
        }
        __syncthreads();
        // write packed layout: float2 index o2 = ((cg*4+i)*4+cp)*16 + dq
        float2* dst = (float2*)(g_Wp + k * 4096);
        #pragma unroll
        for (int j = 0; j < 8; j++) {
            const int o2 = j * 256 + tid;
            const int dq = o2 & 15;
            const int cp = (o2 >> 4) & 3;
            const int i  = (o2 >> 6) & 3;
            const int cg = o2 >> 8;
            const int c0 = 8 * cg + 2 * cp;
            const int d  = 16 * i + dq;
            dst[o2] = make_float2(ts[c0 * 68 + d], ts[(c0 + 1) * 68 + d]);
        }
        return;
    }
    // detect int64 vs int32 neighbor indices
    if (tid == 0) {
        int is64 = 1;
        #pragma unroll
        for (int i = 0; i < 64; i++) {
            if (nbr[2 * i + 1] != 0u) { is64 = 0; break; }
        }
        g_idx_is64 = is64;
    }
}

// ---------------- main fused kernel ----------------
extern "C" __global__ void __launch_bounds__(NTHR, 2)
kpconv_kernel(const float* __restrict__ qpts,
              const float* __restrict__ spts,
              const float* __restrict__ sfeats,
              const void*  __restrict__ nbr,
              const float* __restrict__ kpts,
              float* __restrict__ out)
{
    extern __shared__ float sm[];
    float* w_s   = sm;                          // [MB][HN][16] -> partials [8][16][64]
    float* wgt_s = sm + WS_WORDS;               // [MB][KPN][CIN]
    float* kp_s  = wgt_s + MB * KPN * CIN;      // 48
    float* inv_s = kp_s + 48;                   // MB
    int*   idx_s = (int*)(inv_s + MB);          // [MB][HN]

    const int tid = threadIdx.x;
    const int m0  = blockIdx.x * MB;
    const bool is64 = (g_idx_is64 != 0);

    if (tid < KPN * 3) kp_s[tid] = kpts[tid];
    __syncthreads();

    // ---------------- Stage A: geometry weights w[m,h,k] -> smem ------------
    #pragma unroll
    for (int it = 0; it < 2; it++) {
        const int p = tid + it * NTHR;          // p < MB*HN = 512
        const int m = p >> 5;
        const int h = p & 31;
        const long long gi = (long long)(m0 + m) * HN + h;
        int idx;
        if (is64) idx = (int)((const long long*)nbr)[gi];
        else      idx = ((const int*)nbr)[gi];
        const bool valid = (idx < NSUP);

        float px, py, pz;
        if (valid) {
            const float* s3 = spts + (long long)idx * 3;
            px = s3[0]; py = s3[1]; pz = s3[2];
        } else {
            px = INFPT; py = INFPT; pz = INFPT;
        }
        const float* q3 = qpts + (long long)(m0 + m) * 3;
        const float rx = px - q3[0];
        const float ry = py - q3[1];
        const float rz = pz - q3[2];

        float* wrow = w_s + p * 16;
        float wmax = 0.0f;
        #pragma unroll
        for (int k = 0; k < KPN; k++) {
            const float dx = rx - kp_s[k * 3 + 0];
            const float dy = ry - kp_s[k * 3 + 1];
            const float dz = rz - kp_s[k * 3 + 2];
            const float sq = dx * dx + dy * dy + dz * dz;
            const float w  = fmaxf(1.0f - sqrtf(sq) * 0.5f, 0.0f);
            wrow[k] = w;
            wmax = fmaxf(wmax, w);
        }
        wrow[15] = 0.0f;   // padding slot for k-pair FFMA2

        bool real = false;
        if (valid) real = (g_flags[idx] != 0);
        const unsigned bal = __ballot_sync(0xffffffffu, real);
        if ((tid & 31) == 0) inv_s[m] = 1.0f / (float)max(__popc(bal), 1);

        idx_s[p] = (wmax > 0.0f) ? idx : -1;    // sentinel: skip in stage B
    }
    __syncthreads();

    // ---------------- Stage B: weighted[m,k,c] = sum_h w * f (FFMA2, k-pairs)
    {
        const int g  = tid >> 4;
        const int j  = tid & 15;
        const int c0 = j * 4;

        ull acc2[8][4];
        #pragma unroll
        for (int kp = 0; kp < 8; kp++)
            #pragma unroll
            for (int c = 0; c < 4; c++) acc2[kp][c] = 0ull;

        const int*   irow  = idx_s + g * HN;
        const float* wbase = w_s + g * HN * 16;

        #pragma unroll 4
        for (int h = 0; h < HN; h++) {
            const int idx = irow[h];
            if (idx >= 0) {
                const float4 f = *(const float4*)(sfeats + (long long)idx * CIN + c0);
                ull fd[4];
                fd[0] = dup2(f.x); fd[1] = dup2(f.y); fd[2] = dup2(f.z); fd[3] = dup2(f.w);
                const ull* wr = (const ull*)(wbase + h * 16);
                #pragma unroll
                for (int kp = 0; kp < 8; kp++) {
                    const ull wp = wr[kp];     // (w[2kp], w[2kp+1]) broadcast LDS.64
                    fma2(acc2[kp][0], wp, fd[0]);
                    fma2(acc2[kp][1], wp, fd[1]);
                    fma2(acc2[kp][2], wp, fd[2]);
                    fma2(acc2[kp][3], wp, fd[3]);
                }
            }
        }

        // pack back to wgt_s[g][k][c] with STS.128 (k rows from pair halves)
        float* wgrow = wgt_s + g * KPN * CIN + c0;
        #pragma unroll
        for (int kp = 0; kp < 8; kp++) {
            const float2 v0 = unpk(acc2[kp][0]);
            const float2 v1 = unpk(acc2[kp][1]);
            const float2 v2 = unpk(acc2[kp][2]);
            const float2 v3 = unpk(acc2[kp][3]);
            *(float4*)(wgrow + (2 * kp) * CIN) = make_float4(v0.x, v1.x, v2.x, v3.x);
            if (kp < 7)
                *(float4*)(wgrow + (2 * kp + 1) * CIN) = make_float4(v0.y, v1.y, v2.y, v3.y);
        }
    }
    __syncthreads();   // wgt_s ready; w_s free (stage B done reading w rows)

    // ---------------- Stage C: out[m,d] = sum_{k,c} weighted * W (FFMA2) ----
    {
        const int dq = tid & 15;          // owns d = {dq, dq+16, dq+32, dq+48}
        const int mh = (tid >> 4) & 1;    // query half (8 queries)
        const int cg = tid >> 5;          // channel group of 8
        const int c0 = cg * 8;

        ull acc2[8][4];                   // [q][d-row i]; ull lanes = (even-c, odd-c) partials
        #pragma unroll
        for (int mb = 0; mb < 8; mb++)
            #pragma unroll
            for (int i = 0; i < 4; i++) acc2[mb][i] = 0ull;

        const float* wgbase = wgt_s + (mh * 8) * (KPN * CIN) + c0;

        #pragma unroll 1
        for (int k = 0; k < KPN; k++) {
            // W slice: 16 LDG.64, each a single coalesced 128B line per half-warp
            const float* pk = g_Wp + (k * 8 + cg) * 512 + dq * 2;
            ull wt[4][4];
            #pragma unroll
            for (int i = 0; i < 4; i++) {
                #pragma unroll
                for (int cp = 0; cp < 4; cp++)
                    wt[i][cp] = *(const ull*)(pk + (i * 4 + cp) * 32);
            }
            #pragma unroll
            for (int mb = 0; mb < 8; mb++) {
                const ull* wvp = (const ull*)(wgbase + mb * (KPN * CIN) + k * CIN);
                const ull w0 = wvp[0], w1 = wvp[1], w2 = wvp[2], w3 = wvp[3];
                #pragma unroll
                for (int i = 0; i < 4; i++) {
                    fma2(acc2[mb][i], w0, wt[i][0]);
                    fma2(acc2[mb][i], w1, wt[i][1]);
                    fma2(acc2[mb][i], w2, wt[i][2]);
                    fma2(acc2[mb][i], w3, wt[i][3]);
                }
            }
        }

        // write per-c-group partials into w_s[cg][q][d]
        #pragma unroll
        for (int mb = 0; mb < 8; mb++) {
            #pragma unroll
            for (int i = 0; i < 4; i++) {
                const float2 v = unpk(acc2[mb][i]);
                w_s[cg * 1024 + (mh * 8 + mb) * 64 + i * 16 + dq] = v.x + v.y;
            }
        }
    }
    __syncthreads();

    // final cross-group reduction + normalize + store
    {
        const int mb = tid >> 4;
        const int d0 = (tid & 15) * 4;
        float4 o = make_float4(0.f, 0.f, 0.f, 0.f);
        #pragma unroll
        for (int g8 = 0; g8 < 8; g8++) {
            const float4 p = *(const float4*)(w_s + g8 * 1024 + mb * 64 + d0);
            o.x += p.x; o.y += p.y; o.z += p.z; o.w += p.w;
        }
        const float inv = inv_s[mb];
        o.x *= inv; o.y *= inv; o.z *= inv; o.w *= inv;
        *(float4*)(out + (long long)(m0 + mb) * COUT + d0) = o;
    }
}

extern "C" void kernel_launch(void* const* d_in, const int* in_sizes, int n_in,
                              void* d_out, int out_size) {
    const float* qpts = nullptr;   // 150000
    const float* spts = nullptr;   // 300000
    const float* sfeats = nullptr; // 6400000
    const void*  nbr = nullptr;    // 1600000
    const float* wts = nullptr;    // 61440
    const float* kpts = nullptr;   // 45
    for (int i = 0; i < n_in; i++) {
        switch (in_sizes[i]) {
            case MQ * 3:        qpts   = (const float*)d_in[i]; break;
            case NSUP * 3:      spts   = (const float*)d_in[i]; break;
            case NSUP * CIN:    sfeats = (const float*)d_in[i]; break;
            case MQ * HN:       nbr    = d_in[i];               break;
            case KPN*CIN*COUT:  wts    = (const float*)d_in[i]; break;
            case KPN * 3:       kpts   = (const float*)d_in[i]; break;
            default: break;
        }
    }
    float* outp = (float*)d_out;

    cudaFuncSetAttribute(kpconv_kernel,
                         cudaFuncAttributeMaxDynamicSharedMemorySize, SMEM_BYTES);

    prep_kernel<<<FLAG_BLKS + KPN + 1, 256>>>(sfeats, wts, (const unsigned*)nbr);
    kpconv_kernel<<<MQ / MB, NTHR, SMEM_BYTES>>>(
        qpts, spts, sfeats, nbr, kpts, outp);
}